// round 11
// baseline (speedup 1.0000x reference)
#include <cuda_runtime.h>
#include <cuda_fp16.h>
#include <cstdint>

#define N_NODES 100000
#define N_EDGES 1000000
#define IN_CH 166
#define HID 128
#define KPAD0 192
#define SMS 40        // gemm0 smem row stride (fp16), conflict-free ldmatrix
#define SMSF 136      // fused kernel smem row stride (K=128 + 8 pad)
#define NB ((N_NODES + 255) / 256)
#define TILE_E (128 * SMS)

// ---------------- scratch ------------------------------------------------------
__device__ __half2 g_yh [N_NODES * (HID / 2)];  // layer-0 y (fp16)
__device__ __half2 g_yh2[N_NODES * (HID / 2)];  // layer-1 y (fp16)
__device__ float4  g_z[N_NODES * (HID / 4)];    // self term (fp32, reused both layers)
__device__ float2  g_y2[N_NODES];
__device__ float2  g_z2[N_NODES];
__device__ int g_degi[N_NODES];
__device__ int g_lex[N_NODES];
__device__ int g_bsum[NB];
__device__ int g_boff[NB];
__device__ int g_rowstart[N_NODES + 1];
__device__ int g_cursor[N_NODES];
__device__ int g_csr[N_EDGES];
__device__ __half g_W0[256 * KPAD0];            // layer-0 weights (Wl|Wr), [n][k]
__device__ __half g_W1[256 * HID];              // layer-1 weights (Wl|Wr), [n][k]

// ---------------- helpers ------------------------------------------------------
__device__ __forceinline__ uint32_t smem_u32(const void* p) {
    return (uint32_t)__cvta_generic_to_shared(p);
}
__device__ __forceinline__ void ldsm_x4(uint32_t& r0, uint32_t& r1, uint32_t& r2,
                                        uint32_t& r3, uint32_t addr) {
    asm volatile("ldmatrix.sync.aligned.m8n8.x4.shared.b16 {%0,%1,%2,%3}, [%4];"
                 : "=r"(r0), "=r"(r1), "=r"(r2), "=r"(r3) : "r"(addr));
}
__device__ __forceinline__ void mma_f16(float* d, const uint32_t* a, uint32_t b0, uint32_t b1) {
    asm volatile(
        "mma.sync.aligned.m16n8k16.row.col.f32.f16.f16.f32 "
        "{%0,%1,%2,%3}, {%4,%5,%6,%7}, {%8,%9}, {%0,%1,%2,%3};"
        : "+f"(d[0]), "+f"(d[1]), "+f"(d[2]), "+f"(d[3])
        : "r"(a[0]), "r"(a[1]), "r"(a[2]), "r"(a[3]), "r"(b0), "r"(b1));
}
__device__ __forceinline__ uint32_t packh2(float a, float b) {
    __half2 t = __floats2half2_rn(a, b);
    return *reinterpret_cast<uint32_t*>(&t);
}
__device__ __forceinline__ void cp16z(uint32_t dst, const void* src, int vsz) {
    asm volatile("cp.async.ca.shared.global [%0], [%1], 16, %2;"
                 :: "r"(dst), "l"(src), "r"(vsz));
}
__device__ __forceinline__ void cp_commit() {
    asm volatile("cp.async.commit_group;");
}
template <int N>
__device__ __forceinline__ void cp_wait() {
    asm volatile("cp.async.wait_group %0;" :: "n"(N));
}

// ---------------- CSR build ----------------------------------------------------
__global__ __launch_bounds__(256) void k_zero_degi() {
    int i = blockIdx.x * blockDim.x + threadIdx.x;
    if (i < N_NODES) g_degi[i] = 0;
}
__global__ __launch_bounds__(256) void k_hist(const int* __restrict__ ei) {
    int e = blockIdx.x * blockDim.x + threadIdx.x;
    if (e >= N_EDGES) return;
    atomicAdd(&g_degi[ei[N_EDGES + e]], 1);
}
__global__ __launch_bounds__(256) void k_scan_block() {
    __shared__ int s[256];
    int i = blockIdx.x * 256 + threadIdx.x;
    int t = threadIdx.x;
    int v = (i < N_NODES) ? g_degi[i] : 0;
    s[t] = v;
    __syncthreads();
#pragma unroll
    for (int off = 1; off < 256; off <<= 1) {
        int add = (t >= off) ? s[t - off] : 0;
        __syncthreads();
        s[t] += add;
        __syncthreads();
    }
    if (i < N_NODES) g_lex[i] = s[t] - v;
    if (t == 255) g_bsum[blockIdx.x] = s[255];
}
__global__ __launch_bounds__(512) void k_scan_top() {
    __shared__ int s[512];
    int t = threadIdx.x;
    int v = (t < NB) ? g_bsum[t] : 0;
    s[t] = v;
    __syncthreads();
#pragma unroll
    for (int off = 1; off < 512; off <<= 1) {
        int add = (t >= off) ? s[t - off] : 0;
        __syncthreads();
        s[t] += add;
        __syncthreads();
    }
    if (t < NB) g_boff[t] = s[t] - v;
}
__global__ __launch_bounds__(256) void k_scan_fin() {
    int i = blockIdx.x * 256 + threadIdx.x;
    if (i < N_NODES) {
        int rs = g_lex[i] + g_boff[blockIdx.x];
        g_rowstart[i] = rs;
        g_cursor[i] = rs;
    }
    if (i == 0) g_rowstart[N_NODES] = N_EDGES;
}
__global__ __launch_bounds__(256) void k_fill(const int* __restrict__ ei) {
    int e = blockIdx.x * blockDim.x + threadIdx.x;
    if (e >= N_EDGES) return;
    int s = ei[e];
    int d = ei[N_EDGES + e];
    int pos = atomicAdd(&g_cursor[d], 1);
    g_csr[pos] = s;
}

// ---------------- weight convert (fp32 -> fp16, transposed [n][k]) ------------
__global__ __launch_bounds__(256) void k_cvt_w(const float* __restrict__ Wl,
                                               const float* __restrict__ Wr,
                                               int K, int KP, int which) {
    int i = blockIdx.x * blockDim.x + threadIdx.x;
    if (i >= 256 * KP) return;
    int n = i / KP, k = i - n * KP;
    float v = 0.f;
    if (k < K) v = (n < 128) ? Wl[k * 128 + n] : Wr[k * 128 + (n - 128)];
    __half h = __float2half_rn(v);
    if (which == 0) g_W0[i] = h;
    else            g_W1[i] = h;
}

// ---------------- layer-0 GEMM: fused fp32->fp16 convert during staging -------
// by==0 -> y (fp16 g_yh), by==1 -> z (fp32 g_z)
__global__ __launch_bounds__(256) void tc_gemm0(const float* __restrict__ x, int M) {
    extern __shared__ __half sm[];
    const int tid = threadIdx.x;
    const int lane = tid & 31;
    const int wid = tid >> 5;
    const int warpM = wid >> 1;
    const int warpN = wid & 1;
    const int m0 = blockIdx.x * 128;
    const int by = blockIdx.y;
    const int NK = KPAD0 / 32;   // 6

    const __half* __restrict__ Bg = g_W0 + by * 128 * KPAD0;

    const int srow = tid >> 1;
    const int shalf = (tid & 1) * 16;
    const int so = srow * SMS + shalf;
    const bool arow_ok = (m0 + srow) < M;
    const float* __restrict__ xrow = x + (size_t)(m0 + srow) * IN_CH;
    const size_t brow = (size_t)srow * KPAD0 + shalf;

    auto loadA = [&](int k0, float* r) {
#pragma unroll
        for (int j = 0; j < 8; j++) {
            int c = k0 + shalf + 2 * j;
            float2 v = (arow_ok && c < IN_CH) ? *(const float2*)(xrow + c)
                                              : make_float2(0.f, 0.f);
            r[2 * j] = v.x;
            r[2 * j + 1] = v.y;
        }
    };
    auto storeA = [&](int s, const float* r) {
        __half* base = sm + s * 2 * TILE_E;
        uint4 v0 = make_uint4(packh2(r[0], r[1]),  packh2(r[2], r[3]),
                              packh2(r[4], r[5]),  packh2(r[6], r[7]));
        uint4 v1 = make_uint4(packh2(r[8], r[9]),  packh2(r[10], r[11]),
                              packh2(r[12], r[13]), packh2(r[14], r[15]));
        *(uint4*)(base + so) = v0;
        *(uint4*)(base + so + 8) = v1;
    };
    auto loadB = [&](int s, int k0) {
        __half* base = sm + s * 2 * TILE_E;
        uint32_t dB = smem_u32(base + TILE_E + so);
        cp16z(dB,      Bg + brow + k0, 16);
        cp16z(dB + 16, Bg + brow + k0 + 8, 16);
    };

    float acc[2][8][4];
#pragma unroll
    for (int a = 0; a < 2; a++)
#pragma unroll
        for (int b = 0; b < 8; b++)
#pragma unroll
            for (int c = 0; c < 4; c++) acc[a][b][c] = 0.f;

    float aregs[16], anext[16];
    loadB(0, 0);
    cp_commit();
    loadA(0, aregs);

    for (int it = 0; it < NK; it++) {
        int s = it & 1;
        storeA(s, aregs);
        if (it + 1 < NK) {
            loadB((it + 1) & 1, (it + 1) * 32);
            cp_commit();
            loadA((it + 1) * 32, anext);
            cp_wait<1>();
        } else {
            cp_wait<0>();
        }
        __syncthreads();

        __half* base = sm + s * 2 * TILE_E;
        __half* A_s = base;
        __half* B_s = base + TILE_E;
#pragma unroll
        for (int kk = 0; kk < 32; kk += 16) {
            uint32_t ah[2][4];
#pragma unroll
            for (int mt = 0; mt < 2; mt++) {
                int r = warpM * 32 + mt * 16 + (lane & 15);
                int c = kk + ((lane >> 4) << 3);
                ldsm_x4(ah[mt][0], ah[mt][1], ah[mt][2], ah[mt][3],
                        smem_u32(A_s + r * SMS + c));
            }
#pragma unroll
            for (int g = 0; g < 4; g++) {
                int nrow = warpN * 64 + g * 16 + (lane & 7) + ((lane >> 4) << 3);
                int kc = kk + (((lane >> 3) & 1) << 3);
                uint32_t b0, b1, b2, b3;
                ldsm_x4(b0, b1, b2, b3, smem_u32(B_s + nrow * SMS + kc));
#pragma unroll
                for (int mt = 0; mt < 2; mt++) {
                    mma_f16(acc[mt][g * 2],     ah[mt], b0, b1);
                    mma_f16(acc[mt][g * 2 + 1], ah[mt], b2, b3);
                }
            }
        }
        __syncthreads();
#pragma unroll
        for (int j = 0; j < 16; j++) aregs[j] = anext[j];
    }

#pragma unroll
    for (int mt = 0; mt < 2; mt++) {
#pragma unroll
        for (int j = 0; j < 8; j++) {
            int row = m0 + warpM * 32 + mt * 16 + (lane >> 2);
            int col = warpN * 64 + j * 8 + 2 * (lane & 3);
            if (by == 0) {
                int ci = col >> 1;
                if (row < M)
                    g_yh[row * 64 + ci] = __floats2half2_rn(acc[mt][j][0], acc[mt][j][1]);
                if (row + 8 < M)
                    g_yh[(row + 8) * 64 + ci] = __floats2half2_rn(acc[mt][j][2], acc[mt][j][3]);
            } else {
                float* Cb = (float*)g_z;
                if (row < M)
                    *(float2*)(Cb + (size_t)row * 128 + col) =
                        make_float2(acc[mt][j][0], acc[mt][j][1]);
                if (row + 8 < M)
                    *(float2*)(Cb + (size_t)(row + 8) * 128 + col) =
                        make_float2(acc[mt][j][2], acc[mt][j][3]);
            }
        }
    }
}

// ---------------- FUSED: gather0 (+relu) -> smem A-tile -> layer-1 GEMM --------
// 512 threads. Phase 1: 16 warps x 8 nodes gather h into A_s; W1 cp.async to B_s.
// Phase 2: BM=128 x BN=256 GEMM (y1 -> g_yh2 fp16, z1 -> g_z fp32).
__global__ __launch_bounds__(512) void fused_gather_gemm(const float* __restrict__ bias) {
    extern __shared__ __half sm[];
    __half* A_s = sm;                        // 128 x SMSF
    __half* B_s = sm + 128 * SMSF;           // 256 x SMSF
    const int tid = threadIdx.x;
    const int lane = tid & 31;
    const int wid = tid >> 5;
    const int m0 = blockIdx.x * 128;

    // ---- stream W1 (64 KB = 256 rows x 16 chunks of 16B) into B_s ----
#pragma unroll
    for (int j = 0; j < 8; j++) {
        int idx = j * 512 + tid;             // 4096 16B-chunks total
        int n = idx >> 4, chunk = idx & 15;  // 16 chunks per 128-half row
        cp16z(smem_u32(B_s + n * SMSF + chunk * 8), g_W1 + n * 128 + chunk * 8, 16);
    }
    cp_commit();

    // ---- phase 1: gather h for 8 nodes per warp ----
    const uint2* __restrict__ Y = (const uint2*)g_yh;
#pragma unroll
    for (int i = 0; i < 8; i++) {
        int row = wid * 8 + i;
        int node = m0 + row;
        uint2 st = make_uint2(0u, 0u);
        if (node < N_NODES) {
            int beg = g_rowstart[node];
            int end = g_rowstart[node + 1];
            float4 a0 = make_float4(0.f, 0.f, 0.f, 0.f);
            float4 a1 = make_float4(0.f, 0.f, 0.f, 0.f);
            int e = beg;
            for (; e + 1 < end; e += 2) {
                int s0 = g_csr[e], s1 = g_csr[e + 1];
                uint2 u0 = Y[(size_t)s0 * 32 + lane];
                uint2 u1 = Y[(size_t)s1 * 32 + lane];
                float2 f0 = __half22float2(*reinterpret_cast<__half2*>(&u0.x));
                float2 f1 = __half22float2(*reinterpret_cast<__half2*>(&u0.y));
                float2 f2 = __half22float2(*reinterpret_cast<__half2*>(&u1.x));
                float2 f3 = __half22float2(*reinterpret_cast<__half2*>(&u1.y));
                a0.x += f0.x; a0.y += f0.y; a0.z += f1.x; a0.w += f1.y;
                a1.x += f2.x; a1.y += f2.y; a1.z += f3.x; a1.w += f3.y;
            }
            if (e < end) {
                uint2 u0 = Y[(size_t)g_csr[e] * 32 + lane];
                float2 f0 = __half22float2(*reinterpret_cast<__half2*>(&u0.x));
                float2 f1 = __half22float2(*reinterpret_cast<__half2*>(&u0.y));
                a0.x += f0.x; a0.y += f0.y; a0.z += f1.x; a0.w += f1.y;
            }
            float inv = 1.0f / fmaxf((float)(end - beg), 1.0f);
            float4 z = g_z[node * 32 + lane];
            float4 b = ((const float4*)bias)[lane];
            float rx = fmaxf((a0.x + a1.x) * inv + z.x + b.x, 0.f);
            float ry = fmaxf((a0.y + a1.y) * inv + z.y + b.y, 0.f);
            float rz = fmaxf((a0.z + a1.z) * inv + z.z + b.z, 0.f);
            float rw = fmaxf((a0.w + a1.w) * inv + z.w + b.w, 0.f);
            st.x = packh2(rx, ry);
            st.y = packh2(rz, rw);
        }
        *(uint2*)(A_s + row * SMSF + lane * 4) = st;
    }
    cp_wait<0>();
    __syncthreads();

    // ---- phase 2: GEMM 128x256xK128 ----
    const int warpM = wid >> 2;   // 0..3
    const int warpN = wid & 3;    // 0..3
    float acc[2][8][4];
#pragma unroll
    for (int a = 0; a < 2; a++)
#pragma unroll
        for (int b = 0; b < 8; b++)
#pragma unroll
            for (int c = 0; c < 4; c++) acc[a][b][c] = 0.f;

#pragma unroll
    for (int kk = 0; kk < 128; kk += 16) {
        uint32_t ah[2][4];
#pragma unroll
        for (int mt = 0; mt < 2; mt++) {
            int r = warpM * 32 + mt * 16 + (lane & 15);
            int c = kk + ((lane >> 4) << 3);
            ldsm_x4(ah[mt][0], ah[mt][1], ah[mt][2], ah[mt][3],
                    smem_u32(A_s + r * SMSF + c));
        }
#pragma unroll
        for (int g = 0; g < 4; g++) {
            int nrow = warpN * 64 + g * 16 + (lane & 7) + ((lane >> 4) << 3);
            int kc = kk + (((lane >> 3) & 1) << 3);
            uint32_t b0, b1, b2, b3;
            ldsm_x4(b0, b1, b2, b3, smem_u32(B_s + nrow * SMSF + kc));
#pragma unroll
            for (int mt = 0; mt < 2; mt++) {
                mma_f16(acc[mt][g * 2],     ah[mt], b0, b1);
                mma_f16(acc[mt][g * 2 + 1], ah[mt], b2, b3);
            }
        }
    }

    // ---- epilogue: cols [0,128) -> y1 fp16, cols [128,256) -> z1 fp32 ----
#pragma unroll
    for (int mt = 0; mt < 2; mt++) {
#pragma unroll
        for (int j = 0; j < 8; j++) {
            int row = m0 + warpM * 32 + mt * 16 + (lane >> 2);
            int col = warpN * 64 + j * 8 + 2 * (lane & 3);
            if (col < 128) {
                int ci = col >> 1;
                if (row < N_NODES)
                    g_yh2[row * 64 + ci] = __floats2half2_rn(acc[mt][j][0], acc[mt][j][1]);
                if (row + 8 < N_NODES)
                    g_yh2[(row + 8) * 64 + ci] = __floats2half2_rn(acc[mt][j][2], acc[mt][j][3]);
            } else {
                int zc = col - 128;
                float* Cb = (float*)g_z;
                if (row < N_NODES)
                    *(float2*)(Cb + (size_t)row * 128 + zc) =
                        make_float2(acc[mt][j][0], acc[mt][j][1]);
                if (row + 8 < N_NODES)
                    *(float2*)(Cb + (size_t)(row + 8) * 128 + zc) =
                        make_float2(acc[mt][j][2], acc[mt][j][3]);
            }
        }
    }
}

// ---------------- gather1 + fused head (reads g_yh2) ---------------------------
__global__ __launch_bounds__(256) void k_gather_head(const float* __restrict__ bias,
                                                     const float* __restrict__ Wl2,
                                                     const float* __restrict__ Wr2) {
    int gt = blockIdx.x * blockDim.x + threadIdx.x;
    int node = gt >> 5;
    int lane = gt & 31;
    if (node >= N_NODES) return;
    int beg = g_rowstart[node];
    int end = g_rowstart[node + 1];
    const uint2* __restrict__ Y = (const uint2*)g_yh2;
    float4 a0 = make_float4(0.f, 0.f, 0.f, 0.f);
    float4 a1 = make_float4(0.f, 0.f, 0.f, 0.f);
    int e = beg;
    for (; e + 1 < end; e += 2) {
        int s0 = g_csr[e], s1 = g_csr[e + 1];
        uint2 u0 = Y[(size_t)s0 * 32 + lane];
        uint2 u1 = Y[(size_t)s1 * 32 + lane];
        float2 f0 = __half22float2(*reinterpret_cast<__half2*>(&u0.x));
        float2 f1 = __half22float2(*reinterpret_cast<__half2*>(&u0.y));
        float2 f2 = __half22float2(*reinterpret_cast<__half2*>(&u1.x));
        float2 f3 = __half22float2(*reinterpret_cast<__half2*>(&u1.y));
        a0.x += f0.x; a0.y += f0.y; a0.z += f1.x; a0.w += f1.y;
        a1.x += f2.x; a1.y += f2.y; a1.z += f3.x; a1.w += f3.y;
    }
    if (e < end) {
        uint2 u0 = Y[(size_t)g_csr[e] * 32 + lane];
        float2 f0 = __half22float2(*reinterpret_cast<__half2*>(&u0.x));
        float2 f1 = __half22float2(*reinterpret_cast<__half2*>(&u0.y));
        a0.x += f0.x; a0.y += f0.y; a0.z += f1.x; a0.w += f1.y;
    }
    float inv = 1.0f / fmaxf((float)(end - beg), 1.0f);
    float4 z = g_z[node * 32 + lane];
    float4 b = ((const float4*)bias)[lane];
    float hv[4];
    hv[0] = fmaxf((a0.x + a1.x) * inv + z.x + b.x, 0.f);
    hv[1] = fmaxf((a0.y + a1.y) * inv + z.y + b.y, 0.f);
    hv[2] = fmaxf((a0.z + a1.z) * inv + z.z + b.z, 0.f);
    hv[3] = fmaxf((a0.w + a1.w) * inv + z.w + b.w, 0.f);
    float l0 = 0.f, l1 = 0.f, r0 = 0.f, r1 = 0.f;
#pragma unroll
    for (int j = 0; j < 4; j++) {
        int k = lane * 4 + j;
        l0 += hv[j] * __ldg(&Wl2[k * 2 + 0]);
        l1 += hv[j] * __ldg(&Wl2[k * 2 + 1]);
        r0 += hv[j] * __ldg(&Wr2[k * 2 + 0]);
        r1 += hv[j] * __ldg(&Wr2[k * 2 + 1]);
    }
#pragma unroll
    for (int off = 16; off; off >>= 1) {
        l0 += __shfl_xor_sync(0xffffffffu, l0, off);
        l1 += __shfl_xor_sync(0xffffffffu, l1, off);
        r0 += __shfl_xor_sync(0xffffffffu, r0, off);
        r1 += __shfl_xor_sync(0xffffffffu, r1, off);
    }
    if (lane == 0) {
        g_y2[node] = make_float2(l0, l1);
        g_z2[node] = make_float2(r0, r1);
    }
}

// ---------------- fused layer-2 gather + finalize -> out ----------------------
__global__ __launch_bounds__(256) void k_gather2(const float* __restrict__ bias,
                                                 float* __restrict__ out) {
    int gt = blockIdx.x * blockDim.x + threadIdx.x;
    int node = gt >> 5;
    int lane = gt & 31;
    if (node >= N_NODES) return;
    int beg = g_rowstart[node];
    int end = g_rowstart[node + 1];
    float ax = 0.f, ay = 0.f;
    for (int e = beg + lane; e < end; e += 32) {
        float2 v = g_y2[g_csr[e]];
        ax += v.x;
        ay += v.y;
    }
#pragma unroll
    for (int off = 16; off; off >>= 1) {
        ax += __shfl_xor_sync(0xffffffffu, ax, off);
        ay += __shfl_xor_sync(0xffffffffu, ay, off);
    }
    if (lane == 0) {
        float inv = 1.0f / fmaxf((float)(end - beg), 1.0f);
        float2 z = g_z2[node];
        out[node * 2 + 0] = ax * inv + z.x + bias[0];
        out[node * 2 + 1] = ay * inv + z.y + bias[1];
    }
}

// ---------------- launch -------------------------------------------------------
extern "C" void kernel_launch(void* const* d_in, const int* in_sizes, int n_in,
                              void* d_out, int out_size) {
    const float* x    = (const float*)d_in[0];
    const int*   ei   = (const int*)d_in[1];     // int32 (JAX x64 disabled)
    const float* Wl0  = (const float*)d_in[2];
    const float* bl0  = (const float*)d_in[3];
    const float* Wr0  = (const float*)d_in[4];
    const float* Wl1  = (const float*)d_in[5];
    const float* bl1  = (const float*)d_in[6];
    const float* Wr1  = (const float*)d_in[7];
    const float* Wl2  = (const float*)d_in[8];
    const float* bl2  = (const float*)d_in[9];
    const float* Wr2  = (const float*)d_in[10];
    float*       out  = (float*)d_out;

    const int M = N_NODES;
    const int MB = (M + 127) / 128;              // 782
    dim3 gemm_grid(MB, 2);
    const int WARP_NODES = (N_NODES * 32 + 255) / 256;
    const int SMEM_G0 = 2 * 2 * TILE_E * (int)sizeof(__half);        // 40960
    const int SMEM_FUSED = (128 + 256) * SMSF * (int)sizeof(__half); // 104448

    cudaFuncSetAttribute(tc_gemm0, cudaFuncAttributeMaxDynamicSharedMemorySize, SMEM_G0);
    cudaFuncSetAttribute(fused_gather_gemm, cudaFuncAttributeMaxDynamicSharedMemorySize, SMEM_FUSED);

    // ---- fork: weight converts + CSR build on side stream ----
    cudaStream_t s2;
    cudaStreamCreateWithFlags(&s2, cudaStreamNonBlocking);
    cudaEvent_t evRoot, evW0, evCsr;
    cudaEventCreateWithFlags(&evRoot, cudaEventDisableTiming);
    cudaEventCreateWithFlags(&evW0, cudaEventDisableTiming);
    cudaEventCreateWithFlags(&evCsr, cudaEventDisableTiming);

    cudaEventRecord(evRoot, 0);
    cudaStreamWaitEvent(s2, evRoot, 0);

    k_cvt_w<<<(256 * KPAD0 + 255) / 256, 256, 0, s2>>>(Wl0, Wr0, IN_CH, KPAD0, 0);
    cudaEventRecord(evW0, s2);
    k_zero_degi<<<NB, 256, 0, s2>>>();
    k_hist<<<(N_EDGES + 255) / 256, 256, 0, s2>>>(ei);
    k_scan_block<<<NB, 256, 0, s2>>>();
    k_scan_top<<<1, 512, 0, s2>>>();
    k_scan_fin<<<NB, 256, 0, s2>>>();
    k_fill<<<(N_EDGES + 255) / 256, 256, 0, s2>>>(ei);
    k_cvt_w<<<(256 * HID + 255) / 256, 256, 0, s2>>>(Wl1, Wr1, HID, HID, 1);
    cudaEventRecord(evCsr, s2);

    // ---- main stream ----
    cudaStreamWaitEvent(0, evW0, 0);
    tc_gemm0<<<gemm_grid, 256, SMEM_G0>>>(x, M);          // layer-0 projections
    cudaStreamWaitEvent(0, evCsr, 0);
    fused_gather_gemm<<<MB, 512, SMEM_FUSED>>>(bl0);      // gather0 + layer-1 GEMM
    k_gather_head<<<WARP_NODES, 256>>>(bl1, Wl2, Wr2);    // gather1 + head
    k_gather2<<<WARP_NODES, 256>>>(bl2, out);

    cudaEventDestroy(evRoot);
    cudaEventDestroy(evW0);
    cudaEventDestroy(evCsr);
    cudaStreamDestroy(s2);
}

// round 12
// speedup vs baseline: 1.1727x; 1.1727x over previous
#include <cuda_runtime.h>
#include <cuda_fp16.h>
#include <cstdint>

#define N_NODES 100000
#define N_EDGES 1000000
#define IN_CH 166
#define HID 128
#define KPAD0 192
#define SMS 40      // smem row stride in fp16 (80B = 16B multiple, conflict-free ldmatrix)
#define NB ((N_NODES + 255) / 256)
#define TILE_E (128 * SMS)

// ---------------- scratch ------------------------------------------------------
__device__ __half2 g_yh[N_NODES * (HID / 2)];   // projected neighbor features, fp16
__device__ float4  g_z[N_NODES * (HID / 4)];    // self term, fp32
__device__ float2  g_y2[N_NODES];
__device__ float2  g_z2[N_NODES];
__device__ int g_degi[N_NODES];
__device__ int g_lex[N_NODES];
__device__ int g_bsum[NB];
__device__ int g_boff[NB];
__device__ int g_rowstart[N_NODES + 1];
__device__ int g_cursor[N_NODES];
__device__ int g_csr[N_EDGES];
__device__ __half g_A1[N_NODES * HID];          // layer-1 input h, fp16 (written by gather0)
__device__ __half g_W0[256 * KPAD0];            // layer-0 weights (Wl|Wr), [n][k], fp16
__device__ __half g_W1[256 * HID];              // layer-1 weights, fp16

// ---------------- helpers ------------------------------------------------------
__device__ __forceinline__ uint32_t smem_u32(const void* p) {
    return (uint32_t)__cvta_generic_to_shared(p);
}
__device__ __forceinline__ void ldsm_x4(uint32_t& r0, uint32_t& r1, uint32_t& r2,
                                        uint32_t& r3, uint32_t addr) {
    asm volatile("ldmatrix.sync.aligned.m8n8.x4.shared.b16 {%0,%1,%2,%3}, [%4];"
                 : "=r"(r0), "=r"(r1), "=r"(r2), "=r"(r3) : "r"(addr));
}
__device__ __forceinline__ void mma_f16(float* d, const uint32_t* a, uint32_t b0, uint32_t b1) {
    asm volatile(
        "mma.sync.aligned.m16n8k16.row.col.f32.f16.f16.f32 "
        "{%0,%1,%2,%3}, {%4,%5,%6,%7}, {%8,%9}, {%0,%1,%2,%3};"
        : "+f"(d[0]), "+f"(d[1]), "+f"(d[2]), "+f"(d[3])
        : "r"(a[0]), "r"(a[1]), "r"(a[2]), "r"(a[3]), "r"(b0), "r"(b1));
}
__device__ __forceinline__ uint32_t packh2(float a, float b) {
    __half2 t = __floats2half2_rn(a, b);
    return *reinterpret_cast<uint32_t*>(&t);
}
__device__ __forceinline__ void cp16z(uint32_t dst, const void* src, int vsz) {
    asm volatile("cp.async.ca.shared.global [%0], [%1], 16, %2;"
                 :: "r"(dst), "l"(src), "r"(vsz));
}
__device__ __forceinline__ void cp_commit() {
    asm volatile("cp.async.commit_group;");
}
template <int N>
__device__ __forceinline__ void cp_wait() {
    asm volatile("cp.async.wait_group %0;" :: "n"(N));
}
__device__ __forceinline__ void acc_u2(float4& a, uint2 u) {
    float2 f0 = __half22float2(*reinterpret_cast<__half2*>(&u.x));
    float2 f1 = __half22float2(*reinterpret_cast<__half2*>(&u.y));
    a.x += f0.x; a.y += f0.y; a.z += f1.x; a.w += f1.y;
}

// ---------------- CSR build ----------------------------------------------------
__global__ __launch_bounds__(256) void k_zero_degi() {
    int i = blockIdx.x * blockDim.x + threadIdx.x;
    if (i < N_NODES) g_degi[i] = 0;
}
__global__ __launch_bounds__(256) void k_hist(const int* __restrict__ ei) {
    int e = blockIdx.x * blockDim.x + threadIdx.x;
    if (e >= N_EDGES) return;
    atomicAdd(&g_degi[ei[N_EDGES + e]], 1);
}
__global__ __launch_bounds__(256) void k_scan_block() {
    __shared__ int s[256];
    int i = blockIdx.x * 256 + threadIdx.x;
    int t = threadIdx.x;
    int v = (i < N_NODES) ? g_degi[i] : 0;
    s[t] = v;
    __syncthreads();
#pragma unroll
    for (int off = 1; off < 256; off <<= 1) {
        int add = (t >= off) ? s[t - off] : 0;
        __syncthreads();
        s[t] += add;
        __syncthreads();
    }
    if (i < N_NODES) g_lex[i] = s[t] - v;
    if (t == 255) g_bsum[blockIdx.x] = s[255];
}
__global__ __launch_bounds__(512) void k_scan_top() {
    __shared__ int s[512];
    int t = threadIdx.x;
    int v = (t < NB) ? g_bsum[t] : 0;
    s[t] = v;
    __syncthreads();
#pragma unroll
    for (int off = 1; off < 512; off <<= 1) {
        int add = (t >= off) ? s[t - off] : 0;
        __syncthreads();
        s[t] += add;
        __syncthreads();
    }
    if (t < NB) g_boff[t] = s[t] - v;
}
__global__ __launch_bounds__(256) void k_scan_fin() {
    int i = blockIdx.x * 256 + threadIdx.x;
    if (i < N_NODES) {
        int rs = g_lex[i] + g_boff[blockIdx.x];
        g_rowstart[i] = rs;
        g_cursor[i] = rs;
    }
    if (i == 0) g_rowstart[N_NODES] = N_EDGES;
}
__global__ __launch_bounds__(256) void k_fill(const int* __restrict__ ei) {
    int e = blockIdx.x * blockDim.x + threadIdx.x;
    if (e >= N_EDGES) return;
    int s = ei[e];
    int d = ei[N_EDGES + e];
    int pos = atomicAdd(&g_cursor[d], 1);
    g_csr[pos] = s;
}

// ---------------- weight convert (fp32 -> fp16, transposed [n][k]) ------------
__global__ __launch_bounds__(256) void k_cvt_w(const float* __restrict__ Wl,
                                               const float* __restrict__ Wr,
                                               int K, int KP, int which) {
    int i = blockIdx.x * blockDim.x + threadIdx.x;
    if (i >= 256 * KP) return;
    int n = i / KP, k = i - n * KP;
    float v = 0.f;
    if (k < K) v = (n < 128) ? Wl[k * 128 + n] : Wr[k * 128 + (n - 128)];
    __half h = __float2half_rn(v);
    if (which == 0) g_W0[i] = h;
    else            g_W1[i] = h;
}

// ---------------- GEMM epilogue (shared) --------------------------------------
__device__ __forceinline__ void gemm_epilogue(float acc[2][8][4], int m0, int by,
                                              int warpM, int warpN, int lane, int M) {
#pragma unroll
    for (int mt = 0; mt < 2; mt++) {
#pragma unroll
        for (int j = 0; j < 8; j++) {
            int row = m0 + warpM * 32 + mt * 16 + (lane >> 2);
            int col = warpN * 64 + j * 8 + 2 * (lane & 3);
            if (by == 0) {
                int ci = col >> 1;
                if (row < M)
                    g_yh[row * 64 + ci] = __floats2half2_rn(acc[mt][j][0], acc[mt][j][1]);
                if (row + 8 < M)
                    g_yh[(row + 8) * 64 + ci] = __floats2half2_rn(acc[mt][j][2], acc[mt][j][3]);
            } else {
                float* Cb = (float*)g_z;
                if (row < M)
                    *(float2*)(Cb + (size_t)row * 128 + col) =
                        make_float2(acc[mt][j][0], acc[mt][j][1]);
                if (row + 8 < M)
                    *(float2*)(Cb + (size_t)(row + 8) * 128 + col) =
                        make_float2(acc[mt][j][2], acc[mt][j][3]);
            }
        }
    }
}

// ---------------- shared GEMM compute loop ------------------------------------
__device__ __forceinline__ void gemm_tile_compute(const __half* A_s, const __half* B_s,
                                                  float acc[2][8][4],
                                                  int warpM, int warpN, int lane) {
#pragma unroll
    for (int kk = 0; kk < 32; kk += 16) {
        uint32_t ah[2][4];
#pragma unroll
        for (int mt = 0; mt < 2; mt++) {
            int r = warpM * 32 + mt * 16 + (lane & 15);
            int c = kk + ((lane >> 4) << 3);
            ldsm_x4(ah[mt][0], ah[mt][1], ah[mt][2], ah[mt][3],
                    smem_u32(A_s + r * SMS + c));
        }
#pragma unroll
        for (int g = 0; g < 4; g++) {
            int nrow = warpN * 64 + g * 16 + (lane & 7) + ((lane >> 4) << 3);
            int kc = kk + (((lane >> 3) & 1) << 3);
            uint32_t b0, b1, b2, b3;
            ldsm_x4(b0, b1, b2, b3, smem_u32(B_s + nrow * SMS + kc));
#pragma unroll
            for (int mt = 0; mt < 2; mt++) {
                mma_f16(acc[mt][g * 2],     ah[mt], b0, b1);
                mma_f16(acc[mt][g * 2 + 1], ah[mt], b2, b3);
            }
        }
    }
}

// ---------------- layer-0 GEMM: fused fp32->fp16 convert during staging -------
__global__ __launch_bounds__(256) void tc_gemm0(const float* __restrict__ x, int M) {
    extern __shared__ __half sm[];
    const int tid = threadIdx.x;
    const int lane = tid & 31;
    const int wid = tid >> 5;
    const int warpM = wid >> 1;
    const int warpN = wid & 1;
    const int m0 = blockIdx.x * 128;
    const int by = blockIdx.y;
    const int NK = KPAD0 / 32;   // 6

    const __half* __restrict__ Bg = g_W0 + by * 128 * KPAD0;

    const int srow = tid >> 1;
    const int shalf = (tid & 1) * 16;
    const int so = srow * SMS + shalf;
    const bool arow_ok = (m0 + srow) < M;
    const float* __restrict__ xrow = x + (size_t)(m0 + srow) * IN_CH;
    const size_t brow = (size_t)srow * KPAD0 + shalf;

    auto loadA = [&](int k0, float* r) {
#pragma unroll
        for (int j = 0; j < 8; j++) {
            int c = k0 + shalf + 2 * j;
            float2 v = (arow_ok && c < IN_CH) ? *(const float2*)(xrow + c)
                                              : make_float2(0.f, 0.f);
            r[2 * j] = v.x;
            r[2 * j + 1] = v.y;
        }
    };
    auto storeA = [&](int s, const float* r) {
        __half* base = sm + s * 2 * TILE_E;
        uint4 v0 = make_uint4(packh2(r[0], r[1]),  packh2(r[2], r[3]),
                              packh2(r[4], r[5]),  packh2(r[6], r[7]));
        uint4 v1 = make_uint4(packh2(r[8], r[9]),  packh2(r[10], r[11]),
                              packh2(r[12], r[13]), packh2(r[14], r[15]));
        *(uint4*)(base + so) = v0;
        *(uint4*)(base + so + 8) = v1;
    };
    auto loadB = [&](int s, int k0) {
        __half* base = sm + s * 2 * TILE_E;
        uint32_t dB = smem_u32(base + TILE_E + so);
        cp16z(dB,      Bg + brow + k0, 16);
        cp16z(dB + 16, Bg + brow + k0 + 8, 16);
    };

    float acc[2][8][4];
#pragma unroll
    for (int a = 0; a < 2; a++)
#pragma unroll
        for (int b = 0; b < 8; b++)
#pragma unroll
            for (int c = 0; c < 4; c++) acc[a][b][c] = 0.f;

    float aregs[16], anext[16];
    loadB(0, 0);
    cp_commit();
    loadA(0, aregs);

    for (int it = 0; it < NK; it++) {
        int s = it & 1;
        storeA(s, aregs);
        if (it + 1 < NK) {
            loadB((it + 1) & 1, (it + 1) * 32);
            cp_commit();
            loadA((it + 1) * 32, anext);
            cp_wait<1>();
        } else {
            cp_wait<0>();
        }
        __syncthreads();

        __half* base = sm + s * 2 * TILE_E;
        gemm_tile_compute(base, base + TILE_E, acc, warpM, warpN, lane);
        __syncthreads();
#pragma unroll
        for (int j = 0; j < 16; j++) aregs[j] = anext[j];
    }

    gemm_epilogue(acc, m0, by, warpM, warpN, lane, M);
}

// ---------------- layer-1 GEMM: cp.async from fp16 g_A1 -----------------------
__global__ __launch_bounds__(256) void tc_gemm1(int M) {
    extern __shared__ __half sm[];
    const int tid = threadIdx.x;
    const int lane = tid & 31;
    const int wid = tid >> 5;
    const int warpM = wid >> 1;
    const int warpN = wid & 1;
    const int m0 = blockIdx.x * 128;
    const int by = blockIdx.y;
    const int NK = HID / 32;   // 4

    const __half* __restrict__ Bg = g_W1 + by * 128 * HID;

    const int srow = tid >> 1;
    const int shalf = (tid & 1) * 16;
    const int so = srow * SMS + shalf;
    const int avsz = (m0 + srow < M) ? 16 : 0;
    const size_t arow = (size_t)(m0 + srow) * HID + shalf;
    const size_t brow = (size_t)srow * HID + shalf;

    auto load_stage = [&](int s, int k0) {
        __half* base = sm + s * 2 * TILE_E;
        uint32_t dA = smem_u32(base + so);
        uint32_t dB = smem_u32(base + TILE_E + so);
        cp16z(dA,      g_A1 + arow + k0, avsz);
        cp16z(dA + 16, g_A1 + arow + k0 + 8, avsz);
        cp16z(dB,      Bg + brow + k0, 16);
        cp16z(dB + 16, Bg + brow + k0 + 8, 16);
    };

    float acc[2][8][4];
#pragma unroll
    for (int a = 0; a < 2; a++)
#pragma unroll
        for (int b = 0; b < 8; b++)
#pragma unroll
            for (int c = 0; c < 4; c++) acc[a][b][c] = 0.f;

    load_stage(0, 0);
    cp_commit();

    for (int it = 0; it < NK; it++) {
        if (it + 1 < NK) {
            load_stage((it + 1) & 1, (it + 1) * 32);
            cp_commit();
            cp_wait<1>();
        } else {
            cp_wait<0>();
        }
        __syncthreads();

        __half* base = sm + (it & 1) * 2 * TILE_E;
        gemm_tile_compute(base, base + TILE_E, acc, warpM, warpN, lane);
        __syncthreads();
    }

    gemm_epilogue(acc, m0, by, warpM, warpN, lane, M);
}

// ---------------- fused CSR gather (fp16 y), 4-way unrolled -------------------
template <bool WRITE_H16, bool HEAD>
__global__ __launch_bounds__(256) void k_gather128(const float* __restrict__ bias,
                                                   const float* __restrict__ Wl2,
                                                   const float* __restrict__ Wr2) {
    int gt = blockIdx.x * blockDim.x + threadIdx.x;
    int node = gt >> 5;
    int lane = gt & 31;
    if (node >= N_NODES) return;
    int beg = g_rowstart[node];
    int end = g_rowstart[node + 1];
    const uint2* __restrict__ Y = (const uint2*)g_yh;
    float4 a0 = make_float4(0.f, 0.f, 0.f, 0.f);
    float4 a1 = make_float4(0.f, 0.f, 0.f, 0.f);
    int e = beg;
    for (; e + 3 < end; e += 4) {
        int s0 = g_csr[e], s1 = g_csr[e + 1], s2 = g_csr[e + 2], s3 = g_csr[e + 3];
        uint2 u0 = Y[(size_t)s0 * 32 + lane];
        uint2 u1 = Y[(size_t)s1 * 32 + lane];
        uint2 u2 = Y[(size_t)s2 * 32 + lane];
        uint2 u3 = Y[(size_t)s3 * 32 + lane];
        acc_u2(a0, u0);
        acc_u2(a1, u1);
        acc_u2(a0, u2);
        acc_u2(a1, u3);
    }
    for (; e < end; e++) {
        uint2 u0 = Y[(size_t)g_csr[e] * 32 + lane];
        acc_u2(a0, u0);
    }
    float inv = 1.0f / fmaxf((float)(end - beg), 1.0f);
    float4 z = g_z[node * 32 + lane];
    float4 b = ((const float4*)bias)[lane];
    float4 r;
    r.x = fmaxf((a0.x + a1.x) * inv + z.x + b.x, 0.f);
    r.y = fmaxf((a0.y + a1.y) * inv + z.y + b.y, 0.f);
    r.z = fmaxf((a0.z + a1.z) * inv + z.z + b.z, 0.f);
    r.w = fmaxf((a0.w + a1.w) * inv + z.w + b.w, 0.f);
    if (WRITE_H16) {
        uint2 st;
        st.x = packh2(r.x, r.y);
        st.y = packh2(r.z, r.w);
        *(uint2*)(g_A1 + node * 128 + lane * 4) = st;
    }
    if (HEAD) {
        float hv[4] = {r.x, r.y, r.z, r.w};
        float l0 = 0.f, l1 = 0.f, r0 = 0.f, r1 = 0.f;
#pragma unroll
        for (int j = 0; j < 4; j++) {
            int k = lane * 4 + j;
            l0 += hv[j] * __ldg(&Wl2[k * 2 + 0]);
            l1 += hv[j] * __ldg(&Wl2[k * 2 + 1]);
            r0 += hv[j] * __ldg(&Wr2[k * 2 + 0]);
            r1 += hv[j] * __ldg(&Wr2[k * 2 + 1]);
        }
#pragma unroll
        for (int off = 16; off; off >>= 1) {
            l0 += __shfl_xor_sync(0xffffffffu, l0, off);
            l1 += __shfl_xor_sync(0xffffffffu, l1, off);
            r0 += __shfl_xor_sync(0xffffffffu, r0, off);
            r1 += __shfl_xor_sync(0xffffffffu, r1, off);
        }
        if (lane == 0) {
            g_y2[node] = make_float2(l0, l1);
            g_z2[node] = make_float2(r0, r1);
        }
    }
}

// ---------------- fused layer-2 gather + finalize -> out ----------------------
__global__ __launch_bounds__(256) void k_gather2(const float* __restrict__ bias,
                                                 float* __restrict__ out) {
    int gt = blockIdx.x * blockDim.x + threadIdx.x;
    int node = gt >> 5;
    int lane = gt & 31;
    if (node >= N_NODES) return;
    int beg = g_rowstart[node];
    int end = g_rowstart[node + 1];
    float ax = 0.f, ay = 0.f;
    for (int e = beg + lane; e < end; e += 32) {
        float2 v = g_y2[g_csr[e]];
        ax += v.x;
        ay += v.y;
    }
#pragma unroll
    for (int off = 16; off; off >>= 1) {
        ax += __shfl_xor_sync(0xffffffffu, ax, off);
        ay += __shfl_xor_sync(0xffffffffu, ay, off);
    }
    if (lane == 0) {
        float inv = 1.0f / fmaxf((float)(end - beg), 1.0f);
        float2 z = g_z2[node];
        out[node * 2 + 0] = ax * inv + z.x + bias[0];
        out[node * 2 + 1] = ay * inv + z.y + bias[1];
    }
}

// ---------------- launch -------------------------------------------------------
extern "C" void kernel_launch(void* const* d_in, const int* in_sizes, int n_in,
                              void* d_out, int out_size) {
    const float* x    = (const float*)d_in[0];
    const int*   ei   = (const int*)d_in[1];     // int32 (JAX x64 disabled)
    const float* Wl0  = (const float*)d_in[2];
    const float* bl0  = (const float*)d_in[3];
    const float* Wr0  = (const float*)d_in[4];
    const float* Wl1  = (const float*)d_in[5];
    const float* bl1  = (const float*)d_in[6];
    const float* Wr1  = (const float*)d_in[7];
    const float* Wl2  = (const float*)d_in[8];
    const float* bl2  = (const float*)d_in[9];
    const float* Wr2  = (const float*)d_in[10];
    float*       out  = (float*)d_out;

    const int M = N_NODES;
    dim3 gemm_grid((M + 127) / 128, 2);
    const int WARP_NODES = (N_NODES * 32 + 255) / 256;
    const int SMEM_BYTES = 2 * 2 * TILE_E * (int)sizeof(__half);  // 40960

    cudaFuncSetAttribute(tc_gemm0, cudaFuncAttributeMaxDynamicSharedMemorySize, SMEM_BYTES);
    cudaFuncSetAttribute(tc_gemm1, cudaFuncAttributeMaxDynamicSharedMemorySize, SMEM_BYTES);

    // ---- fork: weight converts + CSR build on side stream ----
    cudaStream_t s2;
    cudaStreamCreateWithFlags(&s2, cudaStreamNonBlocking);
    cudaEvent_t evRoot, evW0, evCsr;
    cudaEventCreateWithFlags(&evRoot, cudaEventDisableTiming);
    cudaEventCreateWithFlags(&evW0, cudaEventDisableTiming);
    cudaEventCreateWithFlags(&evCsr, cudaEventDisableTiming);

    cudaEventRecord(evRoot, 0);
    cudaStreamWaitEvent(s2, evRoot, 0);

    k_cvt_w<<<(256 * KPAD0 + 255) / 256, 256, 0, s2>>>(Wl0, Wr0, IN_CH, KPAD0, 0);
    cudaEventRecord(evW0, s2);
    k_zero_degi<<<NB, 256, 0, s2>>>();
    k_hist<<<(N_EDGES + 255) / 256, 256, 0, s2>>>(ei);
    k_scan_block<<<NB, 256, 0, s2>>>();
    k_scan_top<<<1, 512, 0, s2>>>();
    k_scan_fin<<<NB, 256, 0, s2>>>();
    k_fill<<<(N_EDGES + 255) / 256, 256, 0, s2>>>(ei);
    k_cvt_w<<<(256 * HID + 255) / 256, 256, 0, s2>>>(Wl1, Wr1, HID, HID, 1);
    cudaEventRecord(evCsr, s2);

    // ---- main stream ----
    cudaStreamWaitEvent(0, evW0, 0);
    tc_gemm0<<<gemm_grid, 256, SMEM_BYTES>>>(x, M);     // fused cvt + GEMM
    cudaStreamWaitEvent(0, evCsr, 0);
    k_gather128<true, false><<<WARP_NODES, 256>>>(bl0, nullptr, nullptr);
    tc_gemm1<<<gemm_grid, 256, SMEM_BYTES>>>(M);
    k_gather128<false, true><<<WARP_NODES, 256>>>(bl1, Wl2, Wr2);
    k_gather2<<<WARP_NODES, 256>>>(bl2, out);

    cudaEventDestroy(evRoot);
    cudaEventDestroy(evW0);
    cudaEventDestroy(evCsr);
    cudaStreamDestroy(s2);
}

// round 13
// speedup vs baseline: 1.2066x; 1.0289x over previous
#include <cuda_runtime.h>
#include <cuda_fp16.h>
#include <cstdint>

#define N_NODES 100000
#define N_EDGES 1000000
#define IN_CH 166
#define HID 128
#define KPAD0 192
#define SMS 40      // smem row stride in fp16 (80B = 16B multiple, conflict-free ldmatrix)
#define NB ((N_NODES + 255) / 256)

// ---------------- scratch ------------------------------------------------------
__device__ __half2 g_yh[N_NODES * (HID / 2)];   // projected neighbor features, fp16
__device__ float4  g_z[N_NODES * (HID / 4)];    // self term, fp32
__device__ float2  g_y2[N_NODES];
__device__ float2  g_z2[N_NODES];
__device__ int g_degi[N_NODES];
__device__ int g_lex[N_NODES];
__device__ int g_bsum[NB];
__device__ int g_boff[NB];
__device__ int g_rowstart[N_NODES + 1];
__device__ int g_cursor[N_NODES];
__device__ int g_csr[N_EDGES];
__device__ __half g_A1[N_NODES * HID];          // layer-1 input h, fp16 (written by gather0)
__device__ __half g_W0[256 * KPAD0];            // layer-0 weights (Wl|Wr), [n][k], fp16
__device__ __half g_W1[256 * HID];              // layer-1 weights, fp16

// ---------------- helpers ------------------------------------------------------
__device__ __forceinline__ uint32_t smem_u32(const void* p) {
    return (uint32_t)__cvta_generic_to_shared(p);
}
__device__ __forceinline__ void ldsm_x4(uint32_t& r0, uint32_t& r1, uint32_t& r2,
                                        uint32_t& r3, uint32_t addr) {
    asm volatile("ldmatrix.sync.aligned.m8n8.x4.shared.b16 {%0,%1,%2,%3}, [%4];"
                 : "=r"(r0), "=r"(r1), "=r"(r2), "=r"(r3) : "r"(addr));
}
__device__ __forceinline__ void mma_f16(float* d, const uint32_t* a, uint32_t b0, uint32_t b1) {
    asm volatile(
        "mma.sync.aligned.m16n8k16.row.col.f32.f16.f16.f32 "
        "{%0,%1,%2,%3}, {%4,%5,%6,%7}, {%8,%9}, {%0,%1,%2,%3};"
        : "+f"(d[0]), "+f"(d[1]), "+f"(d[2]), "+f"(d[3])
        : "r"(a[0]), "r"(a[1]), "r"(a[2]), "r"(a[3]), "r"(b0), "r"(b1));
}
__device__ __forceinline__ uint32_t packh2(float a, float b) {
    __half2 t = __floats2half2_rn(a, b);
    return *reinterpret_cast<uint32_t*>(&t);
}
__device__ __forceinline__ void cp16z(uint32_t dst, const void* src, int vsz) {
    asm volatile("cp.async.ca.shared.global [%0], [%1], 16, %2;"
                 :: "r"(dst), "l"(src), "r"(vsz));
}
__device__ __forceinline__ void cp_commit() {
    asm volatile("cp.async.commit_group;");
}
template <int N>
__device__ __forceinline__ void cp_wait() {
    asm volatile("cp.async.wait_group %0;" :: "n"(N));
}
__device__ __forceinline__ void acc_u2(float4& a, uint2 u) {
    float2 f0 = __half22float2(*reinterpret_cast<__half2*>(&u.x));
    float2 f1 = __half22float2(*reinterpret_cast<__half2*>(&u.y));
    a.x += f0.x; a.y += f0.y; a.z += f1.x; a.w += f1.y;
}

// ---------------- CSR build ----------------------------------------------------
__global__ __launch_bounds__(256) void k_hist(const int* __restrict__ ei) {
    int e = blockIdx.x * blockDim.x + threadIdx.x;
    if (e >= N_EDGES) return;
    atomicAdd(&g_degi[ei[N_EDGES + e]], 1);
}
// consumes g_degi and re-zeros it for the next replay (globals start zeroed)
__global__ __launch_bounds__(256) void k_scan_block() {
    __shared__ int s[256];
    int i = blockIdx.x * 256 + threadIdx.x;
    int t = threadIdx.x;
    int v = (i < N_NODES) ? g_degi[i] : 0;
    if (i < N_NODES) g_degi[i] = 0;
    s[t] = v;
    __syncthreads();
#pragma unroll
    for (int off = 1; off < 256; off <<= 1) {
        int add = (t >= off) ? s[t - off] : 0;
        __syncthreads();
        s[t] += add;
        __syncthreads();
    }
    if (i < N_NODES) g_lex[i] = s[t] - v;
    if (t == 255) g_bsum[blockIdx.x] = s[255];
}
__global__ __launch_bounds__(512) void k_scan_top() {
    __shared__ int s[512];
    int t = threadIdx.x;
    int v = (t < NB) ? g_bsum[t] : 0;
    s[t] = v;
    __syncthreads();
#pragma unroll
    for (int off = 1; off < 512; off <<= 1) {
        int add = (t >= off) ? s[t - off] : 0;
        __syncthreads();
        s[t] += add;
        __syncthreads();
    }
    if (t < NB) g_boff[t] = s[t] - v;
}
__global__ __launch_bounds__(256) void k_scan_fin() {
    int i = blockIdx.x * 256 + threadIdx.x;
    if (i < N_NODES) {
        int rs = g_lex[i] + g_boff[blockIdx.x];
        g_rowstart[i] = rs;
        g_cursor[i] = rs;
    }
    if (i == 0) g_rowstart[N_NODES] = N_EDGES;
}
__global__ __launch_bounds__(256) void k_fill(const int* __restrict__ ei) {
    int e = blockIdx.x * blockDim.x + threadIdx.x;
    if (e >= N_EDGES) return;
    int s = ei[e];
    int d = ei[N_EDGES + e];
    int pos = atomicAdd(&g_cursor[d], 1);
    g_csr[pos] = s;
}

// ---------------- weight convert (fp32 -> fp16, transposed [n][k]) ------------
__global__ __launch_bounds__(256) void k_cvt_w(const float* __restrict__ Wl,
                                               const float* __restrict__ Wr,
                                               int K, int KP, int which) {
    int i = blockIdx.x * blockDim.x + threadIdx.x;
    if (i >= 256 * KP) return;
    int n = i / KP, k = i - n * KP;
    float v = 0.f;
    if (k < K) v = (n < 128) ? Wl[k * 128 + n] : Wr[k * 128 + (n - 128)];
    __half h = __float2half_rn(v);
    if (which == 0) g_W0[i] = h;
    else            g_W1[i] = h;
}

// ---------------- merged BN=256 GEMM machinery ---------------------------------
// smem: A stages at s*128*SMS; B stages at 2*128*SMS + s*256*SMS. 61440 bytes.
#define A_TILE (128 * SMS)
#define B_TILE (256 * SMS)
#define SMEM_GEMM ((2 * A_TILE + 2 * B_TILE) * (int)sizeof(__half))

// compute one BK=32 step: A 128 x 32, B 256 x 32; 16 warps as 4M x 4N
__device__ __forceinline__ void gemm_tile_compute256(const __half* A_s, const __half* B_s,
                                                     float acc[2][8][4],
                                                     int warpM, int warpN, int lane) {
#pragma unroll
    for (int kk = 0; kk < 32; kk += 16) {
        uint32_t ah[2][4];
#pragma unroll
        for (int mt = 0; mt < 2; mt++) {
            int r = warpM * 32 + mt * 16 + (lane & 15);
            int c = kk + ((lane >> 4) << 3);
            ldsm_x4(ah[mt][0], ah[mt][1], ah[mt][2], ah[mt][3],
                    smem_u32(A_s + r * SMS + c));
        }
#pragma unroll
        for (int g = 0; g < 4; g++) {
            int nrow = warpN * 64 + g * 16 + (lane & 7) + ((lane >> 4) << 3);
            int kc = kk + (((lane >> 3) & 1) << 3);
            uint32_t b0, b1, b2, b3;
            ldsm_x4(b0, b1, b2, b3, smem_u32(B_s + nrow * SMS + kc));
#pragma unroll
            for (int mt = 0; mt < 2; mt++) {
                mma_f16(acc[mt][g * 2],     ah[mt], b0, b1);
                mma_f16(acc[mt][g * 2 + 1], ah[mt], b2, b3);
            }
        }
    }
}

// epilogue: cols [0,128) -> y fp16 (g_yh), cols [128,256) -> z fp32 (g_z)
__device__ __forceinline__ void gemm_epilogue256(float acc[2][8][4], int m0,
                                                 int warpM, int warpN, int lane, int M) {
#pragma unroll
    for (int mt = 0; mt < 2; mt++) {
#pragma unroll
        for (int j = 0; j < 8; j++) {
            int row = m0 + warpM * 32 + mt * 16 + (lane >> 2);
            int col = warpN * 64 + j * 8 + 2 * (lane & 3);
            if (col < 128) {
                int ci = col >> 1;
                if (row < M)
                    g_yh[row * 64 + ci] = __floats2half2_rn(acc[mt][j][0], acc[mt][j][1]);
                if (row + 8 < M)
                    g_yh[(row + 8) * 64 + ci] = __floats2half2_rn(acc[mt][j][2], acc[mt][j][3]);
            } else {
                int zc = col - 128;
                float* Cb = (float*)g_z;
                if (row < M)
                    *(float2*)(Cb + (size_t)row * 128 + zc) =
                        make_float2(acc[mt][j][0], acc[mt][j][1]);
                if (row + 8 < M)
                    *(float2*)(Cb + (size_t)(row + 8) * 128 + zc) =
                        make_float2(acc[mt][j][2], acc[mt][j][3]);
            }
        }
    }
}

// ---------------- layer-0 GEMM: BN=256, fused fp32->fp16 convert ---------------
__global__ __launch_bounds__(512) void tc_gemm0(const float* __restrict__ x, int M) {
    extern __shared__ __half sm[];
    const int tid = threadIdx.x;
    const int lane = tid & 31;
    const int wid = tid >> 5;
    const int warpM = wid >> 2;
    const int warpN = wid & 3;
    const int m0 = blockIdx.x * 128;
    const int NK = KPAD0 / 32;   // 6

    // A staging: thread -> (arow, 8 cols)
    const int arow = tid >> 2;           // 0..127
    const int aq = tid & 3;              // col group of 8
    const bool arow_ok = (m0 + arow) < M;
    const float* __restrict__ xrow = x + (size_t)(m0 + arow) * IN_CH;
    // B staging: thread -> (brow, 16 cols)
    const int brow = tid >> 1;           // 0..255
    const int bq = tid & 1;              // 0 or 1 (16-col half)
    const size_t bsrc = (size_t)brow * KPAD0 + bq * 16;
    const int bso = brow * SMS + bq * 16;

    auto loadA = [&](int k0, float* r) {
#pragma unroll
        for (int j = 0; j < 4; j++) {
            int c = k0 + aq * 8 + 2 * j;
            float2 v = (arow_ok && c < IN_CH) ? *(const float2*)(xrow + c)
                                              : make_float2(0.f, 0.f);
            r[2 * j] = v.x;
            r[2 * j + 1] = v.y;
        }
    };
    auto storeA = [&](int s, const float* r) {
        __half* base = sm + s * A_TILE;
        uint4 v = make_uint4(packh2(r[0], r[1]), packh2(r[2], r[3]),
                             packh2(r[4], r[5]), packh2(r[6], r[7]));
        *(uint4*)(base + arow * SMS + aq * 8) = v;
    };
    auto loadB = [&](int s, int k0) {
        __half* base = sm + 2 * A_TILE + s * B_TILE;
        cp16z(smem_u32(base + bso), g_W0 + bsrc + k0, 16);
        cp16z(smem_u32(base + bso + 8), g_W0 + bsrc + k0 + 8, 16);
    };

    float acc[2][8][4];
#pragma unroll
    for (int a = 0; a < 2; a++)
#pragma unroll
        for (int b = 0; b < 8; b++)
#pragma unroll
            for (int c = 0; c < 4; c++) acc[a][b][c] = 0.f;

    float aregs[8], anext[8];
    loadB(0, 0);
    cp_commit();
    loadA(0, aregs);

    for (int it = 0; it < NK; it++) {
        int s = it & 1;
        storeA(s, aregs);
        if (it + 1 < NK) {
            loadB((it + 1) & 1, (it + 1) * 32);
            cp_commit();
            loadA((it + 1) * 32, anext);
            cp_wait<1>();
        } else {
            cp_wait<0>();
        }
        __syncthreads();

        gemm_tile_compute256(sm + s * A_TILE, sm + 2 * A_TILE + s * B_TILE,
                             acc, warpM, warpN, lane);
        __syncthreads();
#pragma unroll
        for (int j = 0; j < 8; j++) aregs[j] = anext[j];
    }

    gemm_epilogue256(acc, m0, warpM, warpN, lane, M);
}

// ---------------- layer-1 GEMM: BN=256, cp.async from fp16 g_A1 ---------------
__global__ __launch_bounds__(512) void tc_gemm1(int M) {
    extern __shared__ __half sm[];
    const int tid = threadIdx.x;
    const int lane = tid & 31;
    const int wid = tid >> 5;
    const int warpM = wid >> 2;
    const int warpN = wid & 3;
    const int m0 = blockIdx.x * 128;
    const int NK = HID / 32;   // 4

    const int arow = tid >> 2;
    const int aq = tid & 3;
    const int avsz = (m0 + arow < M) ? 16 : 0;
    const size_t asrc = (size_t)(m0 + arow) * HID + aq * 8;
    const int aso = arow * SMS + aq * 8;
    const int brow = tid >> 1;
    const int bq = tid & 1;
    const size_t bsrc = (size_t)brow * HID + bq * 16;
    const int bso = brow * SMS + bq * 16;

    auto load_stage = [&](int s, int k0) {
        __half* Ab = sm + s * A_TILE;
        __half* Bb = sm + 2 * A_TILE + s * B_TILE;
        cp16z(smem_u32(Ab + aso), g_A1 + asrc + k0, avsz);
        cp16z(smem_u32(Bb + bso), g_W1 + bsrc + k0, 16);
        cp16z(smem_u32(Bb + bso + 8), g_W1 + bsrc + k0 + 8, 16);
    };

    float acc[2][8][4];
#pragma unroll
    for (int a = 0; a < 2; a++)
#pragma unroll
        for (int b = 0; b < 8; b++)
#pragma unroll
            for (int c = 0; c < 4; c++) acc[a][b][c] = 0.f;

    load_stage(0, 0);
    cp_commit();

    for (int it = 0; it < NK; it++) {
        if (it + 1 < NK) {
            load_stage((it + 1) & 1, (it + 1) * 32);
            cp_commit();
            cp_wait<1>();
        } else {
            cp_wait<0>();
        }
        __syncthreads();

        int s = it & 1;
        gemm_tile_compute256(sm + s * A_TILE, sm + 2 * A_TILE + s * B_TILE,
                             acc, warpM, warpN, lane);
        __syncthreads();
    }

    gemm_epilogue256(acc, m0, warpM, warpN, lane, M);
}

// ---------------- fused CSR gather (fp16 y), 4-way unrolled -------------------
template <bool WRITE_H16, bool HEAD>
__global__ __launch_bounds__(256) void k_gather128(const float* __restrict__ bias,
                                                   const float* __restrict__ Wl2,
                                                   const float* __restrict__ Wr2) {
    int gt = blockIdx.x * blockDim.x + threadIdx.x;
    int node = gt >> 5;
    int lane = gt & 31;
    if (node >= N_NODES) return;
    int beg = g_rowstart[node];
    int end = g_rowstart[node + 1];
    const uint2* __restrict__ Y = (const uint2*)g_yh;
    float4 a0 = make_float4(0.f, 0.f, 0.f, 0.f);
    float4 a1 = make_float4(0.f, 0.f, 0.f, 0.f);
    int e = beg;
    for (; e + 3 < end; e += 4) {
        int s0 = g_csr[e], s1 = g_csr[e + 1], s2 = g_csr[e + 2], s3 = g_csr[e + 3];
        uint2 u0 = Y[(size_t)s0 * 32 + lane];
        uint2 u1 = Y[(size_t)s1 * 32 + lane];
        uint2 u2 = Y[(size_t)s2 * 32 + lane];
        uint2 u3 = Y[(size_t)s3 * 32 + lane];
        acc_u2(a0, u0);
        acc_u2(a1, u1);
        acc_u2(a0, u2);
        acc_u2(a1, u3);
    }
    for (; e < end; e++) {
        uint2 u0 = Y[(size_t)g_csr[e] * 32 + lane];
        acc_u2(a0, u0);
    }
    float inv = 1.0f / fmaxf((float)(end - beg), 1.0f);
    float4 z = g_z[node * 32 + lane];
    float4 b = ((const float4*)bias)[lane];
    float4 r;
    r.x = fmaxf((a0.x + a1.x) * inv + z.x + b.x, 0.f);
    r.y = fmaxf((a0.y + a1.y) * inv + z.y + b.y, 0.f);
    r.z = fmaxf((a0.z + a1.z) * inv + z.z + b.z, 0.f);
    r.w = fmaxf((a0.w + a1.w) * inv + z.w + b.w, 0.f);
    if (WRITE_H16) {
        uint2 st;
        st.x = packh2(r.x, r.y);
        st.y = packh2(r.z, r.w);
        *(uint2*)(g_A1 + node * 128 + lane * 4) = st;
    }
    if (HEAD) {
        float hv[4] = {r.x, r.y, r.z, r.w};
        float l0 = 0.f, l1 = 0.f, r0 = 0.f, r1 = 0.f;
#pragma unroll
        for (int j = 0; j < 4; j++) {
            int k = lane * 4 + j;
            l0 += hv[j] * __ldg(&Wl2[k * 2 + 0]);
            l1 += hv[j] * __ldg(&Wl2[k * 2 + 1]);
            r0 += hv[j] * __ldg(&Wr2[k * 2 + 0]);
            r1 += hv[j] * __ldg(&Wr2[k * 2 + 1]);
        }
#pragma unroll
        for (int off = 16; off; off >>= 1) {
            l0 += __shfl_xor_sync(0xffffffffu, l0, off);
            l1 += __shfl_xor_sync(0xffffffffu, l1, off);
            r0 += __shfl_xor_sync(0xffffffffu, r0, off);
            r1 += __shfl_xor_sync(0xffffffffu, r1, off);
        }
        if (lane == 0) {
            g_y2[node] = make_float2(l0, l1);
            g_z2[node] = make_float2(r0, r1);
        }
    }
}

// ---------------- fused layer-2 gather + finalize -> out ----------------------
__global__ __launch_bounds__(256) void k_gather2(const float* __restrict__ bias,
                                                 float* __restrict__ out) {
    int gt = blockIdx.x * blockDim.x + threadIdx.x;
    int node = gt >> 5;
    int lane = gt & 31;
    if (node >= N_NODES) return;
    int beg = g_rowstart[node];
    int end = g_rowstart[node + 1];
    float ax = 0.f, ay = 0.f;
    for (int e = beg + lane; e < end; e += 32) {
        float2 v = g_y2[g_csr[e]];
        ax += v.x;
        ay += v.y;
    }
#pragma unroll
    for (int off = 16; off; off >>= 1) {
        ax += __shfl_xor_sync(0xffffffffu, ax, off);
        ay += __shfl_xor_sync(0xffffffffu, ay, off);
    }
    if (lane == 0) {
        float inv = 1.0f / fmaxf((float)(end - beg), 1.0f);
        float2 z = g_z2[node];
        out[node * 2 + 0] = ax * inv + z.x + bias[0];
        out[node * 2 + 1] = ay * inv + z.y + bias[1];
    }
}

// ---------------- launch -------------------------------------------------------
extern "C" void kernel_launch(void* const* d_in, const int* in_sizes, int n_in,
                              void* d_out, int out_size) {
    const float* x    = (const float*)d_in[0];
    const int*   ei   = (const int*)d_in[1];     // int32 (JAX x64 disabled)
    const float* Wl0  = (const float*)d_in[2];
    const float* bl0  = (const float*)d_in[3];
    const float* Wr0  = (const float*)d_in[4];
    const float* Wl1  = (const float*)d_in[5];
    const float* bl1  = (const float*)d_in[6];
    const float* Wr1  = (const float*)d_in[7];
    const float* Wl2  = (const float*)d_in[8];
    const float* bl2  = (const float*)d_in[9];
    const float* Wr2  = (const float*)d_in[10];
    float*       out  = (float*)d_out;

    const int M = N_NODES;
    const int MB = (M + 127) / 128;              // 782
    const int WARP_NODES = (N_NODES * 32 + 255) / 256;

    cudaFuncSetAttribute(tc_gemm0, cudaFuncAttributeMaxDynamicSharedMemorySize, SMEM_GEMM);
    cudaFuncSetAttribute(tc_gemm1, cudaFuncAttributeMaxDynamicSharedMemorySize, SMEM_GEMM);

    // ---- fork: weight converts + CSR build on side stream ----
    cudaStream_t s2;
    cudaStreamCreateWithFlags(&s2, cudaStreamNonBlocking);
    cudaEvent_t evRoot, evW0, evCsr;
    cudaEventCreateWithFlags(&evRoot, cudaEventDisableTiming);
    cudaEventCreateWithFlags(&evW0, cudaEventDisableTiming);
    cudaEventCreateWithFlags(&evCsr, cudaEventDisableTiming);

    cudaEventRecord(evRoot, 0);
    cudaStreamWaitEvent(s2, evRoot, 0);

    k_cvt_w<<<(256 * KPAD0 + 255) / 256, 256, 0, s2>>>(Wl0, Wr0, IN_CH, KPAD0, 0);
    cudaEventRecord(evW0, s2);
    k_hist<<<(N_EDGES + 255) / 256, 256, 0, s2>>>(ei);
    k_scan_block<<<NB, 256, 0, s2>>>();
    k_scan_top<<<1, 512, 0, s2>>>();
    k_scan_fin<<<NB, 256, 0, s2>>>();
    k_fill<<<(N_EDGES + 255) / 256, 256, 0, s2>>>(ei);
    k_cvt_w<<<(256 * HID + 255) / 256, 256, 0, s2>>>(Wl1, Wr1, HID, HID, 1);
    cudaEventRecord(evCsr, s2);

    // ---- main stream ----
    cudaStreamWaitEvent(0, evW0, 0);
    tc_gemm0<<<MB, 512, SMEM_GEMM>>>(x, M);             // y0 + z0 in one grid
    cudaStreamWaitEvent(0, evCsr, 0);
    k_gather128<true, false><<<WARP_NODES, 256>>>(bl0, nullptr, nullptr);
    tc_gemm1<<<MB, 512, SMEM_GEMM>>>(M);                // y1 + z1 in one grid
    k_gather128<false, true><<<WARP_NODES, 256>>>(bl1, Wl2, Wr2);
    k_gather2<<<WARP_NODES, 256>>>(bl2, out);

    cudaEventDestroy(evRoot);
    cudaEventDestroy(evW0);
    cudaEventDestroy(evCsr);
    cudaStreamDestroy(s2);
}